// round 16
// baseline (speedup 1.0000x reference)
#include <cuda_runtime.h>
#include <cuda_fp16.h>
#include <cstdint>
#include <cstddef>

#define HEADS 24
#define HEAD_DIM 128
#define INNER 3072
#define RANK 1024
#define S_IMG 2048
#define S_TXT 512
#define S_REF 2048
#define SQ (S_TXT + S_IMG)          // 2560
#define SK (S_TXT + S_IMG + S_REF)  // 4608

// ---------------- scratch (device globals; no allocation) ----------------
__device__ __half g_x16[(size_t)(S_IMG + S_TXT + S_REF) * INNER];
__device__ __half g_tk16[(size_t)S_REF * RANK];
__device__ __half g_tv16[(size_t)S_REF * RANK];
__device__ __half g_o16[(size_t)SQ * INNER];
__device__ __half g_qpre[(size_t)SQ * INNER];
__device__ __half g_kpre[(size_t)SK * INNER];
__device__ __half g_q16[(size_t)SQ * INNER];
__device__ __half g_k16[(size_t)SK * INNER];
__device__ __half g_v16[(size_t)SK * INNER];

// ---------------- multi-descriptor fp32->fp16 convert (activations) ------
struct CvtDesc { const float* src; __half* dst; int bstart; };
struct CvtArgs { CvtDesc d[3]; int nd; };

__global__ __launch_bounds__(256) void cvt_multi_kernel(CvtArgs args)
{
    int bid = blockIdx.x;
    int p = 0;
    if (args.nd > 1 && args.d[1].bstart <= bid) p = 1;
    if (args.nd > 2 && args.d[2].bstart <= bid) p = 2;
    const CvtDesc& d = args.d[p];

    size_t i = ((size_t)(bid - d.bstart) * 256 + threadIdx.x) * 8;
    float4 v0 = *(const float4*)(d.src + i);
    float4 v1 = *(const float4*)(d.src + i + 4);
    __half2* yp = (__half2*)(d.dst + i);
    yp[0] = __floats2half2_rn(v0.x, v0.y);
    yp[1] = __floats2half2_rn(v0.z, v0.w);
    yp[2] = __floats2half2_rn(v1.x, v1.y);
    yp[3] = __floats2half2_rn(v1.z, v1.w);
}

// ---------------- ptx helpers ----------------
#define LDSM4(R, addr) \
    asm volatile("ldmatrix.sync.aligned.m8n8.x4.shared.b16 {%0,%1,%2,%3},[%4];" \
        : "=r"((R)[0]), "=r"((R)[1]), "=r"((R)[2]), "=r"((R)[3]) : "r"(addr))
#define LDSM4T(R, addr) \
    asm volatile("ldmatrix.sync.aligned.m8n8.x4.trans.shared.b16 {%0,%1,%2,%3},[%4];" \
        : "=r"((R)[0]), "=r"((R)[1]), "=r"((R)[2]), "=r"((R)[3]) : "r"(addr))
#define MMA_F16(C, A, B) \
    asm volatile("mma.sync.aligned.m16n8k16.row.col.f32.f16.f16.f32 " \
        "{%0,%1,%2,%3},{%4,%5,%6,%7},{%8,%9},{%0,%1,%2,%3};" \
        : "+f"((C)[0]), "+f"((C)[1]), "+f"((C)[2]), "+f"((C)[3]) \
        : "r"((A)[0]), "r"((A)[1]), "r"((A)[2]), "r"((A)[3]), "r"((B)[0]), "r"((B)[1]))
#define MMA_F16_B2(C, A, B0, B1) \
    asm volatile("mma.sync.aligned.m16n8k16.row.col.f32.f16.f16.f32 " \
        "{%0,%1,%2,%3},{%4,%5,%6,%7},{%8,%9},{%0,%1,%2,%3};" \
        : "+f"((C)[0]), "+f"((C)[1]), "+f"((C)[2]), "+f"((C)[3]) \
        : "r"((A)[0]), "r"((A)[1]), "r"((A)[2]), "r"((A)[3]), "r"(B0), "r"(B1))

__device__ __forceinline__ void cp16(const void* dst, const void* src) {
    unsigned d = (unsigned)__cvta_generic_to_shared(dst);
    asm volatile("cp.async.cg.shared.global [%0],[%1],16;" :: "r"(d), "l"(src));
}
#define CP_COMMIT() asm volatile("cp.async.commit_group;")
#define CP_WAIT0()  asm volatile("cp.async.wait_group 0;")
#define CP_WAIT1()  asm volatile("cp.async.wait_group 1;")

// ---------------- batched fp16-A x fp32-B GEMM (up to 3 sub-problems) ----
// B is fp32, converted in-register during the stage fill (same rounding as
// the old cvt kernel). Segments select per-segment original weight arrays.
#define A_LD 40
#define B_LD 136
#define SA_ELEMS (128 * A_LD)
#define SB_ELEMS (32 * B_LD)
#define GSTAGE (SA_ELEMS + SB_ELEMS)
#define GEMM_SMEM_BYTES (GSTAGE * 3 * 2)

struct GDesc {
    const __half* A;
    const float *B0, *B1, *B2;        // per-segment fp32 weights [K, SEGW]
    const float *b0, *b1, *b2;
    __half *C0, *C1, *C2;
    float *Cf;
    int M, N, K, SEGW, bstart;
};
struct GArgs { GDesc g[3]; int ng; };

__global__ __launch_bounds__(256, 1) void gemm_multi_kernel(GArgs args)
{
    extern __shared__ __half dsm[];
    int bid = blockIdx.x;
    int p = 0;
    if (args.ng > 1 && args.g[1].bstart <= bid) p = 1;
    if (args.ng > 2 && args.g[2].bstart <= bid) p = 2;
    const GDesc& d = args.g[p];

    const int nbx  = d.N >> 7;
    const int loc  = bid - d.bstart;
    const int bn   = (loc % nbx) * 128;
    const int bm   = (loc / nbx) * 128;
    const int K    = d.K;

    const int seg  = bn / d.SEGW;
    const float* Bf = (seg == 0) ? d.B0 : (seg == 1) ? d.B1 : d.B2;
    const int bnl  = bn - seg * d.SEGW;
    const int ldb  = d.SEGW;

    const int tid  = threadIdx.x;
    const int lane = tid & 31;
    const int wid  = tid >> 5;
    const int wm   = wid & 3;
    const int wn   = wid >> 2;
    const int ar = tid >> 1, ac = (tid & 1) * 16;
    const int br = tid >> 4, bc = (tid & 15) * 8;

    float c[2][8][4];
#pragma unroll
    for (int mi = 0; mi < 2; mi++)
#pragma unroll
        for (int ni = 0; ni < 8; ni++)
#pragma unroll
            for (int r = 0; r < 4; r++) c[mi][ni][r] = 0.f;

    const int iters = K >> 5;
    const __half* A = d.A;

    float4 rb0, rb1, rb2, rb3;   // B register staging (fp32)
    auto ldgB = [&](int it) {
        int k0 = it << 5;
        const float* p0 = Bf + (size_t)(k0 + br) * ldb + bnl + bc;
        const float* p1 = Bf + (size_t)(k0 + br + 16) * ldb + bnl + bc;
        rb0 = *(const float4*)p0; rb1 = *(const float4*)(p0 + 4);
        rb2 = *(const float4*)p1; rb3 = *(const float4*)(p1 + 4);
    };
    auto stsB = [&](int s) {
        __half* pB = dsm + s * GSTAGE + SA_ELEMS;
        __half2 h[4];
        h[0] = __floats2half2_rn(rb0.x, rb0.y); h[1] = __floats2half2_rn(rb0.z, rb0.w);
        h[2] = __floats2half2_rn(rb1.x, rb1.y); h[3] = __floats2half2_rn(rb1.z, rb1.w);
        *(uint4*)(pB + br * B_LD + bc) = *(uint4*)h;
        h[0] = __floats2half2_rn(rb2.x, rb2.y); h[1] = __floats2half2_rn(rb2.z, rb2.w);
        h[2] = __floats2half2_rn(rb3.x, rb3.y); h[3] = __floats2half2_rn(rb3.z, rb3.w);
        *(uint4*)(pB + (br + 16) * B_LD + bc) = *(uint4*)h;
    };
    auto loadA = [&](int s, int it) {
        int k0 = it << 5;
        __half* st = dsm + s * GSTAGE;
        cp16(st + ar * A_LD + ac,     A + (size_t)(bm + ar) * K + k0 + ac);
        cp16(st + ar * A_LD + ac + 8, A + (size_t)(bm + ar) * K + k0 + ac + 8);
    };

    // prologue
    ldgB(0);
    loadA(0, 0); CP_COMMIT();
    stsB(0);                 // no reader until after first sync
    ldgB(1);
    loadA(1, 1); CP_COMMIT();

    for (int it = 0; it < iters; it++) {
        if (it == iters - 1) { CP_WAIT0(); } else { CP_WAIT1(); }
        __syncthreads();
        if (it + 1 < iters) stsB((it + 1) % 3);           // B for next iter
        if (it + 2 < iters) {
            ldgB(it + 2);
            loadA((it + 2) % 3, it + 2); CP_COMMIT();
        }

        const __half* st = dsm + (it % 3) * GSTAGE;
        const unsigned sA_b = (unsigned)__cvta_generic_to_shared(st);
        const unsigned sB_b = sA_b + SA_ELEMS * 2;

#pragma unroll
        for (int kh = 0; kh < 2; kh++) {
            unsigned af[2][4];
#pragma unroll
            for (int mi = 0; mi < 2; mi++) {
                unsigned off = (unsigned)(((wm * 32 + mi * 16 + (lane & 15)) * A_LD
                                           + kh * 16 + ((lane >> 4) << 3)) * 2);
                LDSM4(af[mi], sA_b + off);
            }
#pragma unroll
            for (int pp = 0; pp < 4; pp++) {
                unsigned bh[4];
                unsigned off = (unsigned)(((kh * 16 + (lane & 15)) * B_LD
                                           + wn * 64 + pp * 16 + ((lane >> 4) << 3)) * 2);
                LDSM4T(bh, sB_b + off);
#pragma unroll
                for (int mi = 0; mi < 2; mi++) {
                    MMA_F16(c[mi][2 * pp],     af[mi], bh);
                    MMA_F16(c[mi][2 * pp + 1], af[mi], bh + 2);
                }
            }
        }
    }

    const int row0 = bm + wm * 32 + (lane >> 2);
    if (d.Cf) {
        const int col0 = bn + wn * 64 + (lane & 3) * 2;
#pragma unroll
        for (int mi = 0; mi < 2; mi++) {
#pragma unroll
            for (int ni = 0; ni < 8; ni++) {
                int r  = row0 + mi * 16;
                int cc = col0 + ni * 8;
                float b0v = d.b0 ? d.b0[cc] : 0.f;
                float b1v = d.b0 ? d.b0[cc + 1] : 0.f;
                *(float2*)(d.Cf + (size_t)r * d.N + cc) =
                    float2{c[mi][ni][0] + b0v, c[mi][ni][1] + b1v};
                *(float2*)(d.Cf + (size_t)(r + 8) * d.N + cc) =
                    float2{c[mi][ni][2] + b0v, c[mi][ni][3] + b1v};
            }
        }
    } else {
        __half* dst = (seg == 0) ? d.C0 : (seg == 1) ? d.C1 : d.C2;
        const float* bias = (seg == 0) ? d.b0 : (seg == 1) ? d.b1 : d.b2;
        const int col0 = bnl + wn * 64 + (lane & 3) * 2;
#pragma unroll
        for (int mi = 0; mi < 2; mi++) {
#pragma unroll
            for (int ni = 0; ni < 8; ni++) {
                int r  = row0 + mi * 16;
                int cc = col0 + ni * 8;
                float b0v = bias ? bias[cc] : 0.f;
                float b1v = bias ? bias[cc + 1] : 0.f;
                *(__half2*)(dst + (size_t)r * d.SEGW + cc) =
                    __floats2half2_rn(c[mi][ni][0] + b0v, c[mi][ni][1] + b1v);
                *(__half2*)(dst + (size_t)(r + 8) * d.SEGW + cc) =
                    __floats2half2_rn(c[mi][ni][2] + b0v, c[mi][ni][3] + b1v);
            }
        }
    }
}

// ------ fused RMSNorm + RoPE: one WARP per (row, head), 4 dims/lane ------
__global__ __launch_bounds__(256) void rmsnorm_rope_all_kernel(
    const __half* __restrict__ qpre, const __half* __restrict__ kpre,
    __half* __restrict__ q16, __half* __restrict__ k16,
    const float* __restrict__ naq_w, const float* __restrict__ nq_w,
    const float* __restrict__ nak_w, const float* __restrict__ nk_w,
    const float* __restrict__ rcos, const float* __restrict__ rsin,
    const float* __restrict__ ccos, const float* __restrict__ csin)
{
    const int wg   = blockIdx.x * 8 + (threadIdx.x >> 5);
    const int lane = threadIdx.x & 31;
    const int rr   = wg / HEADS;
    const int h    = wg - rr * HEADS;
    const int d0   = lane * 4;

    const __half* src; __half* dst;
    const float *w, *cos_t, *sin_t;
    float eps;
    int row;
    if (rr < SQ) {
        row = rr; src = qpre; dst = q16;
        w = (row < S_TXT) ? naq_w : nq_w;
        cos_t = rcos; sin_t = rsin; eps = 1e-6f;
    } else if (rr < 2 * SQ) {
        row = rr - SQ; src = kpre; dst = k16;
        w = (row < S_TXT) ? nak_w : nk_w;
        cos_t = rcos; sin_t = rsin; eps = 1e-6f;
    } else {
        row = rr - 2 * SQ;
        src = kpre + (size_t)SQ * INNER; dst = k16 + (size_t)SQ * INNER;
        w = nullptr; cos_t = ccos; sin_t = csin; eps = 1e-5f;
    }

    const size_t base = (size_t)row * INNER + h * HEAD_DIM + d0;
    __half2 hv[2];
    *(uint2*)hv = *(const uint2*)(src + base);
    float x0 = __half2float(hv[0].x), x1 = __half2float(hv[0].y);
    float x2 = __half2float(hv[1].x), x3 = __half2float(hv[1].y);

    float ss = x0 * x0 + x1 * x1 + x2 * x2 + x3 * x3;
#pragma unroll
    for (int o = 16; o; o >>= 1) ss += __shfl_xor_sync(0xffffffffu, ss, o);
    float r = rsqrtf(ss * (1.0f / HEAD_DIM) + eps);

    float y0 = x0 * r, y1 = x1 * r, y2 = x2 * r, y3 = x3 * r;
    if (w) {
        float4 wv = *(const float4*)(w + d0);
        y0 *= wv.x; y1 *= wv.y; y2 *= wv.z; y3 *= wv.w;
    }

    float4 cv = *(const float4*)(cos_t + (size_t)row * HEAD_DIM + d0);
    float4 sv = *(const float4*)(sin_t + (size_t)row * HEAD_DIM + d0);
    float o0 = y0 * cv.x - y1 * sv.x;
    float o1 = y1 * cv.y + y0 * sv.y;
    float o2 = y2 * cv.z - y3 * sv.z;
    float o3 = y3 * cv.w + y2 * sv.w;

    __half2 out[2];
    out[0] = __floats2half2_rn(o0, o1);
    out[1] = __floats2half2_rn(o2, o3);
    *(uint2*)(dst + base) = *(uint2*)out;
}

// ---------------- tensor-core flash attention (fp16, cp.async KV) --------
#define LDQ 136
#define Q_ELEMS (128 * LDQ)
#define KV_ELEMS (64 * LDQ)
#define KVSTAGE_ELEMS (2 * KV_ELEMS)
#define ATTN_SMEM_BYTES ((Q_ELEMS + 2 * KVSTAGE_ELEMS) * 2)

__global__ __launch_bounds__(256, 2) void attn_fp16_kernel(
    const __half* __restrict__ Q16,
    const __half* __restrict__ K16,
    const __half* __restrict__ V16,
    __half* __restrict__ O16)
{
    extern __shared__ __half smh[];
    __half* sQ = smh;
    __half* kvBase = sQ + Q_ELEMS;

    const int h    = blockIdx.y;
    const int q0   = blockIdx.x * 128;
    const int tid  = threadIdx.x;
    const int lane = tid & 31;
    const int w    = tid >> 5;
    const float scale = 0.08838834764831845f;

    const unsigned sQ_b = (unsigned)__cvta_generic_to_shared(sQ);

    const int krow = tid >> 2;
    const int kcol = (tid & 3) * 32;

    auto load_kv = [&](int s, int kt) {
        __half* st = kvBase + s * KVSTAGE_ELEMS;
        __half* pK = st;
        __half* pV = st + KV_ELEMS;
#pragma unroll
        for (int seg = 0; seg < 4; seg++) {
            int cc = kcol + seg * 8;
            size_t g = (size_t)(kt * 64 + krow) * INNER + h * HEAD_DIM + cc;
            cp16(pK + krow * LDQ + cc, K16 + g);
            cp16(pV + krow * LDQ + cc, V16 + g);
        }
    };

    load_kv(0, 0); CP_COMMIT();

    for (int i = tid; i < 128 * 16; i += 256) {
        int row = i >> 4;
        int c8  = (i & 15) * 8;
        size_t g = (size_t)(q0 + row) * INNER + h * HEAD_DIM + c8;
        *(uint4*)(sQ + row * LDQ + c8) = *(const uint4*)(Q16 + g);
    }

    float o[16][4];
#pragma unroll
    for (int nt = 0; nt < 16; nt++)
#pragma unroll
        for (int r = 0; r < 4; r++) o[nt][r] = 0.f;
    float m_lo = -1e30f, m_hi = -1e30f, l_lo = 0.f, l_hi = 0.f;

    const int NT = SK / 64;
    for (int kt = 0; kt < NT; kt++) {
        CP_WAIT0();
        __syncthreads();
        if (kt + 1 < NT) { load_kv((kt + 1) & 1, kt + 1); CP_COMMIT(); }

        const __half* st = kvBase + (kt & 1) * KVSTAGE_ELEMS;
        const unsigned sK_b = (unsigned)__cvta_generic_to_shared(st);
        const unsigned sV_b = sK_b + KV_ELEMS * 2;

        float c[8][4];
#pragma unroll
        for (int n = 0; n < 8; n++)
#pragma unroll
            for (int r = 0; r < 4; r++) c[n][r] = 0.f;

#pragma unroll
        for (int kk = 0; kk < 8; kk++) {
            unsigned aq[4];
            unsigned qoff = (unsigned)(((w * 16 + (lane & 15)) * LDQ
                                        + kk * 16 + ((lane >> 4) << 3)) * 2);
            LDSM4(aq, sQ_b + qoff);
#pragma unroll
            for (int ng = 0; ng < 4; ng++) {
                unsigned bh[4];
                unsigned koff = (unsigned)(((ng * 16 + (lane & 15)) * LDQ
                                            + kk * 16 + ((lane >> 4) << 3)) * 2);
                LDSM4(bh, sK_b + koff);
                MMA_F16_B2(c[2 * ng],     aq, bh[0], bh[2]);
                MMA_F16_B2(c[2 * ng + 1], aq, bh[1], bh[3]);
            }
        }

        float tmx_lo = -1e30f, tmx_hi = -1e30f;
#pragma unroll
        for (int n = 0; n < 8; n++) {
            c[n][0] *= scale; c[n][1] *= scale; c[n][2] *= scale; c[n][3] *= scale;
            tmx_lo = fmaxf(tmx_lo, fmaxf(c[n][0], c[n][1]));
            tmx_hi = fmaxf(tmx_hi, fmaxf(c[n][2], c[n][3]));
        }
        tmx_lo = fmaxf(tmx_lo, __shfl_xor_sync(0xffffffffu, tmx_lo, 1));
        tmx_lo = fmaxf(tmx_lo, __shfl_xor_sync(0xffffffffu, tmx_lo, 2));
        tmx_hi = fmaxf(tmx_hi, __shfl_xor_sync(0xffffffffu, tmx_hi, 1));
        tmx_hi = fmaxf(tmx_hi, __shfl_xor_sync(0xffffffffu, tmx_hi, 2));

        float mn_lo = fmaxf(m_lo, tmx_lo);
        float mn_hi = fmaxf(m_hi, tmx_hi);
        float al_lo = __expf(m_lo - mn_lo);
        float al_hi = __expf(m_hi - mn_hi);
        m_lo = mn_lo; m_hi = mn_hi;

        unsigned ph[8][2];
        float sum_lo = 0.f, sum_hi = 0.f;
#pragma unroll
        for (int n = 0; n < 8; n++) {
            float p0 = __expf(c[n][0] - m_lo);
            float p1 = __expf(c[n][1] - m_lo);
            float p2 = __expf(c[n][2] - m_hi);
            float p3 = __expf(c[n][3] - m_hi);
            sum_lo += p0 + p1;
            sum_hi += p2 + p3;
            __half2 h01 = __floats2half2_rn(p0, p1);
            __half2 h23 = __floats2half2_rn(p2, p3);
            ph[n][0] = *(unsigned*)&h01; ph[n][1] = *(unsigned*)&h23;
        }
        sum_lo += __shfl_xor_sync(0xffffffffu, sum_lo, 1);
        sum_lo += __shfl_xor_sync(0xffffffffu, sum_lo, 2);
        sum_hi += __shfl_xor_sync(0xffffffffu, sum_hi, 1);
        sum_hi += __shfl_xor_sync(0xffffffffu, sum_hi, 2);
        l_lo = l_lo * al_lo + sum_lo;
        l_hi = l_hi * al_hi + sum_hi;

#pragma unroll
        for (int nt = 0; nt < 16; nt++) {
            o[nt][0] *= al_lo; o[nt][1] *= al_lo;
            o[nt][2] *= al_hi; o[nt][3] *= al_hi;
        }

#pragma unroll
        for (int j = 0; j < 4; j++) {
            unsigned Ap[4] = {ph[2 * j][0], ph[2 * j][1], ph[2 * j + 1][0], ph[2 * j + 1][1]};
#pragma unroll
            for (int dp = 0; dp < 8; dp++) {
                unsigned v4[4];
                unsigned voff = (unsigned)(((j * 16 + (lane & 15)) * LDQ
                                            + dp * 16 + ((lane >> 4) << 3)) * 2);
                LDSM4T(v4, sV_b + voff);
                MMA_F16_B2(o[2 * dp],     Ap, v4[0], v4[1]);
                MMA_F16_B2(o[2 * dp + 1], Ap, v4[2], v4[3]);
            }
        }
        __syncthreads();
    }

    float inv_lo = 1.0f / l_lo;
    float inv_hi = 1.0f / l_hi;
    const int row_lo = q0 + w * 16 + (lane >> 2);
    const int row_hi = row_lo + 8;
    const int cbase  = h * HEAD_DIM + (lane & 3) * 2;
#pragma unroll
    for (int nt = 0; nt < 16; nt++) {
        int d = cbase + nt * 8;
        *(__half2*)(O16 + (size_t)row_lo * INNER + d) =
            __floats2half2_rn(o[nt][0] * inv_lo, o[nt][1] * inv_lo);
        *(__half2*)(O16 + (size_t)row_hi * INNER + d) =
            __floats2half2_rn(o[nt][2] * inv_hi, o[nt][3] * inv_hi);
    }
}

// ---------------- launch ----------------
extern "C" void kernel_launch(void* const* d_in, const int* in_sizes, int n_in,
                              void* d_out, int out_size)
{
    (void)in_sizes; (void)n_in; (void)out_size;
    const float* hid   = (const float*)d_in[0];
    const float* enc   = (const float*)d_in[1];
    const float* ref   = (const float*)d_in[2];
    const float* rcos  = (const float*)d_in[3];
    const float* rsin  = (const float*)d_in[4];
    const float* ccos  = (const float*)d_in[5];
    const float* csin  = (const float*)d_in[6];
    const float* Wq    = (const float*)d_in[7];
    const float* bq    = (const float*)d_in[8];
    const float* Wk    = (const float*)d_in[9];
    const float* bk    = (const float*)d_in[10];
    const float* Wv    = (const float*)d_in[11];
    const float* bv    = (const float*)d_in[12];
    const float* Waq   = (const float*)d_in[13];
    const float* baq   = (const float*)d_in[14];
    const float* Wak   = (const float*)d_in[15];
    const float* bak   = (const float*)d_in[16];
    const float* Wav   = (const float*)d_in[17];
    const float* bav   = (const float*)d_in[18];
    const float* Wout  = (const float*)d_in[19];
    const float* bout  = (const float*)d_in[20];
    const float* Wadd  = (const float*)d_in[21];
    const float* badd  = (const float*)d_in[22];
    const float* nq_w  = (const float*)d_in[23];
    const float* nk_w  = (const float*)d_in[24];
    const float* naq_w = (const float*)d_in[25];
    const float* nak_w = (const float*)d_in[26];
    const float* lkd   = (const float*)d_in[27];
    const float* lku   = (const float*)d_in[28];
    const float* lvd   = (const float*)d_in[29];
    const float* lvu   = (const float*)d_in[30];

    __half *x16, *tk16, *tv16, *o16, *qpre, *kpre, *q16, *k16, *v16;
    cudaGetSymbolAddress((void**)&x16, g_x16);
    cudaGetSymbolAddress((void**)&tk16, g_tk16);
    cudaGetSymbolAddress((void**)&tv16, g_tv16);
    cudaGetSymbolAddress((void**)&o16, g_o16);
    cudaGetSymbolAddress((void**)&qpre, g_qpre);
    cudaGetSymbolAddress((void**)&kpre, g_kpre);
    cudaGetSymbolAddress((void**)&q16, g_q16);
    cudaGetSymbolAddress((void**)&k16, g_k16);
    cudaGetSymbolAddress((void**)&v16, g_v16);

    cudaFuncSetAttribute(gemm_multi_kernel, cudaFuncAttributeMaxDynamicSharedMemorySize,
                         GEMM_SMEM_BYTES);
    cudaFuncSetAttribute(attn_fp16_kernel, cudaFuncAttributeMaxDynamicSharedMemorySize,
                         ATTN_SMEM_BYTES);

    const size_t off_hid = 0;
    const size_t off_enc = (size_t)S_IMG * INNER;
    const size_t off_ref = (size_t)(S_IMG + S_TXT) * INNER;

    // ---- activation convert (3 descriptors, one launch) ----
    {
        CvtArgs ca{};
        int cb = 0;
        ca.d[0] = CvtDesc{hid, x16 + off_hid, cb}; cb += (int)(((size_t)S_IMG * INNER) >> 11);
        ca.d[1] = CvtDesc{enc, x16 + off_enc, cb}; cb += (int)(((size_t)S_TXT * INNER) >> 11);
        ca.d[2] = CvtDesc{ref, x16 + off_ref, cb}; cb += (int)(((size_t)S_REF * INNER) >> 11);
        ca.nd = 3;
        cvt_multi_kernel<<<cb, 256>>>(ca);
    }

    // ---- G1: hid QKV + enc QKV + LoRA-down (fp32 weights direct) ----
    {
        GArgs ga{};
        int gb = 0;
        ga.g[0] = GDesc{x16 + off_hid, Wq, Wk, Wv, bq, bk, bv,
                        qpre + (size_t)S_TXT * INNER, kpre + (size_t)S_TXT * INNER,
                        v16 + (size_t)S_TXT * INNER, nullptr,
                        S_IMG, 3 * INNER, INNER, INNER, gb};
        gb += (S_IMG / 128) * (3 * INNER / 128);
        ga.g[1] = GDesc{x16 + off_enc, Waq, Wak, Wav, baq, bak, bav,
                        qpre, kpre, v16, nullptr,
                        S_TXT, 3 * INNER, INNER, INNER, gb};
        gb += (S_TXT / 128) * (3 * INNER / 128);
        ga.g[2] = GDesc{x16 + off_ref, lkd, lvd, nullptr, nullptr, nullptr, nullptr,
                        tk16, tv16, nullptr, nullptr,
                        S_REF, 2 * RANK, INNER, RANK, gb};
        gb += (S_REF / 128) * (2 * RANK / 128);
        ga.ng = 3;
        gemm_multi_kernel<<<gb, 256, GEMM_SMEM_BYTES>>>(ga);
    }

    // ---- G2: LoRA-up k and v ----
    {
        GArgs ga{};
        int gb = 0;
        ga.g[0] = GDesc{tk16, lku, nullptr, nullptr, nullptr, nullptr, nullptr,
                        kpre + (size_t)SQ * INNER, nullptr, nullptr, nullptr,
                        S_REF, INNER, RANK, INNER, gb};
        gb += (S_REF / 128) * (INNER / 128);
        ga.g[1] = GDesc{tv16, lvu, nullptr, nullptr, nullptr, nullptr, nullptr,
                        v16 + (size_t)SQ * INNER, nullptr, nullptr, nullptr,
                        S_REF, INNER, RANK, INNER, gb};
        gb += (S_REF / 128) * (INNER / 128);
        ga.ng = 2;
        gemm_multi_kernel<<<gb, 256, GEMM_SMEM_BYTES>>>(ga);
    }

    // ---- RMSNorm + RoPE (one launch, warp per row-head) ----
    {
        int total_warps = (2 * SQ + S_REF) * HEADS;
        rmsnorm_rope_all_kernel<<<total_warps / 8, 256>>>(
            qpre, kpre, q16, k16, naq_w, nq_w, nak_w, nk_w, rcos, rsin, ccos, csin);
    }

    // ---- attention ----
    attn_fp16_kernel<<<dim3(SQ / 128, HEADS), 256, ATTN_SMEM_BYTES>>>(
        q16, k16, v16, o16);

    // ---- G3: output projections (fp32 out) ----
    {
        float* outp = (float*)d_out;
        GArgs ga{};
        int gb = 0;
        ga.g[0] = GDesc{o16 + (size_t)S_TXT * INNER, Wout, nullptr, nullptr,
                        bout, nullptr, nullptr,
                        nullptr, nullptr, nullptr, outp,
                        S_IMG, INNER, INNER, INNER, gb};
        gb += (S_IMG / 128) * (INNER / 128);
        ga.g[1] = GDesc{o16, Wadd, nullptr, nullptr, badd, nullptr, nullptr,
                        nullptr, nullptr, nullptr, outp + (size_t)S_IMG * INNER,
                        S_TXT, INNER, INNER, INNER, gb};
        gb += (S_TXT / 128) * (INNER / 128);
        ga.ng = 2;
        gemm_multi_kernel<<<gb, 256, GEMM_SMEM_BYTES>>>(ga);
    }
}